// round 1
// baseline (speedup 1.0000x reference)
#include <cuda_runtime.h>
#include <cuda_bf16.h>

#define N_POINTS 1000000
#define GRID_D   128
#define CH       32
#define NVOX     (GRID_D * GRID_D * GRID_D)   // 2,097,152

// Scratch: feature transposed to (D,H,W,C) so one voxel's 32 channels are a
// contiguous 128B line. 256 MB static device array (allowed; not a runtime alloc).
__device__ float g_feat_t[(size_t)NVOX * CH];

// ---------------------------------------------------------------------------
// Kernel 1: transpose (C, V) -> (V, C) with a 32x32 smem tile.
// Read side:  for fixed channel row, 32 consecutive voxels -> coalesced.
// Write side: for fixed voxel row, 32 consecutive channels -> coalesced.
// ---------------------------------------------------------------------------
__global__ void transpose_feat(const float* __restrict__ feature) {
    __shared__ float tile[32][33];
    const int s0 = blockIdx.x * 32;           // voxel tile start
    const int tx = threadIdx.x;               // 0..31
    const int ty = threadIdx.y;               // 0..31 (channel on read)

    // read: channel ty, voxel s0+tx   (coalesced along voxels)
    tile[ty][tx] = __ldg(&feature[(size_t)ty * NVOX + (s0 + tx)]);
    __syncthreads();
    // write: voxel s0+ty, channel tx  (coalesced along channels)
    g_feat_t[(size_t)(s0 + ty) * CH + tx] = tile[tx][ty];
}

// ---------------------------------------------------------------------------
// Kernel 2: trilinear gather. 8 lanes per point; each lane owns 4 channels
// (one float4). Per corner, the 8 lanes of a point read one contiguous 128B
// line. 8 independent corner loads per lane -> MLP=8.
// ---------------------------------------------------------------------------
__global__ void gather_trilinear(const float* __restrict__ x,
                                 float* __restrict__ out) {
    const int tid = blockIdx.x * blockDim.x + threadIdx.x;
    const int p   = tid >> 3;                 // point index
    const int q   = tid & 7;                  // float4 slot within point
    if (p >= N_POINTS) return;

    const float px = __ldg(&x[3 * p + 0]);
    const float py = __ldg(&x[3 * p + 1]);
    const float pz = __ldg(&x[3 * p + 2]);

    // fx = ((2*(x-LO)/(HI-LO) - 1 + 1)*W - 1)*0.5 = x*6.4 + 63.5  (LO=-10,HI=10,W=128)
    const float fx = fmaf(px, 6.4f, 63.5f);
    const float fy = fmaf(py, 6.4f, 63.5f);
    const float fz = fmaf(pz, 6.4f, 63.5f);

    const float x0f = floorf(fx), y0f = floorf(fy), z0f = floorf(fz);
    const float wx = fx - x0f, wy = fy - y0f, wz = fz - z0f;
    const int x0 = (int)x0f, y0 = (int)y0f, z0 = (int)z0f;

    float4 acc = make_float4(0.f, 0.f, 0.f, 0.f);
    const int cg = q * 4;                     // channel offset of this lane's float4

    #pragma unroll
    for (int dz = 0; dz < 2; ++dz) {
        const int   zi = z0 + dz;
        const bool  vz = (zi >= 0) && (zi < GRID_D);
        const int   cz = min(max(zi, 0), GRID_D - 1);
        const float wzt = dz ? wz : 1.0f - wz;
        #pragma unroll
        for (int dy = 0; dy < 2; ++dy) {
            const int   yi = y0 + dy;
            const bool  vy = (yi >= 0) && (yi < GRID_D);
            const int   cy = min(max(yi, 0), GRID_D - 1);
            const float wyt = dy ? wy : 1.0f - wy;
            #pragma unroll
            for (int dx = 0; dx < 2; ++dx) {
                const int   xi = x0 + dx;
                const bool  vx = (xi >= 0) && (xi < GRID_D);
                const int   cx = min(max(xi, 0), GRID_D - 1);
                const float wxt = dx ? wx : 1.0f - wx;

                const float w = (vx && vy && vz) ? (wxt * wyt * wzt) : 0.0f;
                const int idx = ((cz * GRID_D + cy) * GRID_D + cx) * CH + cg;
                const float4 v = *reinterpret_cast<const float4*>(&g_feat_t[idx]);
                acc.x = fmaf(w, v.x, acc.x);
                acc.y = fmaf(w, v.y, acc.y);
                acc.z = fmaf(w, v.z, acc.z);
                acc.w = fmaf(w, v.w, acc.w);
            }
        }
    }

    reinterpret_cast<float4*>(out)[(size_t)p * 8 + q] = acc;
}

extern "C" void kernel_launch(void* const* d_in, const int* in_sizes, int n_in,
                              void* d_out, int out_size) {
    const float* x       = (const float*)d_in[0];   // (N_POINTS, 3)
    const float* feature = (const float*)d_in[1];   // (32, 128, 128, 128)
    float*       out     = (float*)d_out;           // (N_POINTS, 32)

    // 1) transpose feature to voxel-major
    dim3 tb(32, 32);
    transpose_feat<<<NVOX / 32, tb>>>(feature);

    // 2) gather: 8 lanes per point
    const int total   = N_POINTS * 8;
    const int threads = 256;
    gather_trilinear<<<(total + threads - 1) / threads, threads>>>(x, out);
}

// round 2
// speedup vs baseline: 1.6720x; 1.6720x over previous
#include <cuda_runtime.h>
#include <cuda_bf16.h>

#define N_POINTS 1000000
#define GRID_D   128
#define CH       32
#define NVOX     (GRID_D * GRID_D * GRID_D)   // 2,097,152

// Feature transposed to (D,H,W,C): one voxel's 32 channels = contiguous 128B.
__device__ float g_feat_t[(size_t)NVOX * CH];

// ---------------------------------------------------------------------------
// Kernel 1: transpose (C, V) -> (V, C).
// Block = 256 threads, tile = 256 voxels x 32 channels (32 KB smem).
// Read:  8x LDG.128/thread, coalesced (warp reads 512B runs), MLP=8.
// smem:  XOR-swizzled (col ^ ((ch>>2)*4)) -> conflict-free stores AND reads.
// Write: float4 of 4 channels per voxel, STG.128, warp = 4 full 128B lines.
// ---------------------------------------------------------------------------
__global__ __launch_bounds__(256) void transpose_feat(const float* __restrict__ feature) {
    __shared__ float tile[32 * 256];          // [ch][col], pitch 256 floats
    const int t  = threadIdx.x;
    const int s0 = blockIdx.x * 256;          // voxel tile start

    // ---- read phase: batch all 8 loads for MLP ----
    float4 v[8];
    #pragma unroll
    for (int r = 0; r < 8; ++r) {
        const int i  = r * 256 + t;           // 0..2047 float4 slots
        const int ch = i >> 6;                // 64 float4 per channel row
        const int c4 = i & 63;                // float4 index within 256 voxels
        v[r] = __ldg(reinterpret_cast<const float4*>(
                  &feature[(size_t)ch * NVOX + s0 + c4 * 4]));
    }
    #pragma unroll
    for (int r = 0; r < 8; ++r) {
        const int i   = r * 256 + t;
        const int ch  = i >> 6;
        const int c4  = i & 63;
        const int col = (c4 * 4) ^ ((ch >> 2) * 4);   // swizzled, float4-aligned
        *reinterpret_cast<float4*>(&tile[ch * 256 + col]) = v[r];
    }
    __syncthreads();

    // ---- write phase: voxel-major float4 of channels ----
    #pragma unroll
    for (int r = 0; r < 8; ++r) {
        const int i   = r * 256 + t;          // 0..2047 output float4 slots
        const int vox = i >> 3;               // 0..255
        const int cq  = i & 7;                // which float4 of the 32 channels
        const int col = vox ^ (cq * 4);       // swizzle: ch>>2 == cq for k<4
        float4 o;
        o.x = tile[(cq * 4 + 0) * 256 + col];
        o.y = tile[(cq * 4 + 1) * 256 + col];
        o.z = tile[(cq * 4 + 2) * 256 + col];
        o.w = tile[(cq * 4 + 3) * 256 + col];
        *reinterpret_cast<float4*>(&g_feat_t[(size_t)(s0 + vox) * CH + cq * 4]) = o;
    }
}

// ---------------------------------------------------------------------------
// Kernel 2: trilinear gather. 8 lanes per point; each lane owns one float4
// (4 channels). Per corner the 8 lanes read one contiguous 128B line.
// 8 independent corner loads per lane -> MLP=8. (Measured: DRAM 82.6%.)
// ---------------------------------------------------------------------------
__global__ void gather_trilinear(const float* __restrict__ x,
                                 float* __restrict__ out) {
    const int tid = blockIdx.x * blockDim.x + threadIdx.x;
    const int p   = tid >> 3;                 // point index
    const int q   = tid & 7;                  // float4 slot within point
    if (p >= N_POINTS) return;

    const float px = __ldg(&x[3 * p + 0]);
    const float py = __ldg(&x[3 * p + 1]);
    const float pz = __ldg(&x[3 * p + 2]);

    // fx = x*6.4 + 63.5  (LO=-10, HI=10, W=128)
    const float fx = fmaf(px, 6.4f, 63.5f);
    const float fy = fmaf(py, 6.4f, 63.5f);
    const float fz = fmaf(pz, 6.4f, 63.5f);

    const float x0f = floorf(fx), y0f = floorf(fy), z0f = floorf(fz);
    const float wx = fx - x0f, wy = fy - y0f, wz = fz - z0f;
    const int x0 = (int)x0f, y0 = (int)y0f, z0 = (int)z0f;

    float4 acc = make_float4(0.f, 0.f, 0.f, 0.f);
    const int cg = q * 4;

    #pragma unroll
    for (int dz = 0; dz < 2; ++dz) {
        const int   zi = z0 + dz;
        const bool  vz = (zi >= 0) && (zi < GRID_D);
        const int   cz = min(max(zi, 0), GRID_D - 1);
        const float wzt = dz ? wz : 1.0f - wz;
        #pragma unroll
        for (int dy = 0; dy < 2; ++dy) {
            const int   yi = y0 + dy;
            const bool  vy = (yi >= 0) && (yi < GRID_D);
            const int   cy = min(max(yi, 0), GRID_D - 1);
            const float wyt = dy ? wy : 1.0f - wy;
            #pragma unroll
            for (int dx = 0; dx < 2; ++dx) {
                const int   xi = x0 + dx;
                const bool  vx = (xi >= 0) && (xi < GRID_D);
                const int   cx = min(max(xi, 0), GRID_D - 1);
                const float wxt = dx ? wx : 1.0f - wx;

                const float w = (vx && vy && vz) ? (wxt * wyt * wzt) : 0.0f;
                const int idx = ((cz * GRID_D + cy) * GRID_D + cx) * CH + cg;
                const float4 fv = *reinterpret_cast<const float4*>(&g_feat_t[idx]);
                acc.x = fmaf(w, fv.x, acc.x);
                acc.y = fmaf(w, fv.y, acc.y);
                acc.z = fmaf(w, fv.z, acc.z);
                acc.w = fmaf(w, fv.w, acc.w);
            }
        }
    }

    reinterpret_cast<float4*>(out)[(size_t)p * 8 + q] = acc;
}

extern "C" void kernel_launch(void* const* d_in, const int* in_sizes, int n_in,
                              void* d_out, int out_size) {
    const float* x       = (const float*)d_in[0];   // (N_POINTS, 3)
    const float* feature = (const float*)d_in[1];   // (32, 128, 128, 128)
    float*       out     = (float*)d_out;           // (N_POINTS, 32)

    transpose_feat<<<NVOX / 256, 256>>>(feature);

    const int total   = N_POINTS * 8;
    const int threads = 256;
    gather_trilinear<<<(total + threads - 1) / threads, threads>>>(x, out);
}

// round 3
// speedup vs baseline: 2.4163x; 1.4452x over previous
#include <cuda_runtime.h>
#include <cuda_fp16.h>

#define N_POINTS 1000000
#define GRID_D   128
#define CH       32
#define NVOX     (GRID_D * GRID_D * GRID_D)   // 2,097,152

// Feature transposed to (D,H,W,C) in half: one voxel's 32 channels = 64B.
// 128 MB static array -> grid ~fits L2 (126 MB), gather becomes L2-served.
__device__ __half g_feat_h[(size_t)NVOX * CH];

// ---------------------------------------------------------------------------
// Kernel 1: transpose (C, V) fp32 -> (V, C) fp16.
// Block = 256 threads, tile = 256 voxels x 32 channels (32 KB smem fp32).
// Read:  8x LDG.128/thread coalesced, MLP=8. smem XOR-swizzled.
// Write: per thread 4x uint4 (8 halves = 8 channels of one voxel), coalesced.
// ---------------------------------------------------------------------------
__global__ __launch_bounds__(256) void transpose_feat(const float* __restrict__ feature) {
    __shared__ float tile[32 * 256];          // [ch][col], pitch 256 floats
    const int t  = threadIdx.x;
    const int s0 = blockIdx.x * 256;          // voxel tile start

    // ---- read phase: batch all 8 loads for MLP ----
    float4 v[8];
    #pragma unroll
    for (int r = 0; r < 8; ++r) {
        const int i  = r * 256 + t;           // 0..2047 float4 slots
        const int ch = i >> 6;                // 64 float4 per channel row
        const int c4 = i & 63;
        v[r] = __ldg(reinterpret_cast<const float4*>(
                  &feature[(size_t)ch * NVOX + s0 + c4 * 4]));
    }
    #pragma unroll
    for (int r = 0; r < 8; ++r) {
        const int i   = r * 256 + t;
        const int ch  = i >> 6;
        const int c4  = i & 63;
        const int col = (c4 * 4) ^ ((ch >> 2) * 4);   // swizzled, float4-aligned
        *reinterpret_cast<float4*>(&tile[ch * 256 + col]) = v[r];
    }
    __syncthreads();

    // ---- write phase: per output uint4 = 8 channels (half) of one voxel ----
    // 256 vox * 4 octets = 1024 uint4; 4 per thread.
    #pragma unroll
    for (int r = 0; r < 4; ++r) {
        const int i   = r * 256 + t;          // 0..1023
        const int vox = i >> 2;               // 0..255
        const int oct = i & 3;                // which 8-channel octet
        half2 h[4];
        #pragma unroll
        for (int kk = 0; kk < 4; ++kk) {
            const int ch0 = oct * 8 + kk * 2;
            const int ch1 = ch0 + 1;
            const float a = tile[ch0 * 256 + (vox ^ ((ch0 >> 2) * 4))];
            const float b = tile[ch1 * 256 + (vox ^ ((ch1 >> 2) * 4))];
            h[kk] = __floats2half2_rn(a, b);
        }
        uint4 o;
        o.x = *reinterpret_cast<unsigned*>(&h[0]);
        o.y = *reinterpret_cast<unsigned*>(&h[1]);
        o.z = *reinterpret_cast<unsigned*>(&h[2]);
        o.w = *reinterpret_cast<unsigned*>(&h[3]);
        *reinterpret_cast<uint4*>(&g_feat_h[(size_t)(s0 + vox) * CH + oct * 8]) = o;
    }
}

// ---------------------------------------------------------------------------
// Kernel 2: trilinear gather. 4 lanes per point; each lane owns 8 channels
// (one 16B uint4 per corner). 8 independent corner loads -> MLP=8.
// Accumulate in fp32; output 2x STG.128 per lane (full 128B line per point).
// ---------------------------------------------------------------------------
__global__ __launch_bounds__(256) void gather_trilinear(const float* __restrict__ x,
                                                        float* __restrict__ out) {
    const int tid = blockIdx.x * blockDim.x + threadIdx.x;
    const int p   = tid >> 2;                 // point index
    const int q   = tid & 3;                  // channel octet
    if (p >= N_POINTS) return;

    const float px = __ldg(&x[3 * p + 0]);
    const float py = __ldg(&x[3 * p + 1]);
    const float pz = __ldg(&x[3 * p + 2]);

    // fx = x*6.4 + 63.5  (LO=-10, HI=10, W=128)
    const float fx = fmaf(px, 6.4f, 63.5f);
    const float fy = fmaf(py, 6.4f, 63.5f);
    const float fz = fmaf(pz, 6.4f, 63.5f);

    const float x0f = floorf(fx), y0f = floorf(fy), z0f = floorf(fz);
    const float wx = fx - x0f, wy = fy - y0f, wz = fz - z0f;
    const int x0 = (int)x0f, y0 = (int)y0f, z0 = (int)z0f;

    // per-corner weights + clamped flat indices (computed up-front)
    float  w[8];
    size_t idx[8];
    #pragma unroll
    for (int c = 0; c < 8; ++c) {
        const int dx = c & 1, dy = (c >> 1) & 1, dz = (c >> 2) & 1;
        const int xi = x0 + dx, yi = y0 + dy, zi = z0 + dz;
        const bool vld = (xi >= 0) && (xi < GRID_D) &&
                         (yi >= 0) && (yi < GRID_D) &&
                         (zi >= 0) && (zi < GRID_D);
        const int cx = min(max(xi, 0), GRID_D - 1);
        const int cy = min(max(yi, 0), GRID_D - 1);
        const int cz = min(max(zi, 0), GRID_D - 1);
        const float wxt = dx ? wx : 1.0f - wx;
        const float wyt = dy ? wy : 1.0f - wy;
        const float wzt = dz ? wz : 1.0f - wz;
        w[c]   = vld ? (wxt * wyt * wzt) : 0.0f;
        idx[c] = ((size_t)((cz * GRID_D + cy) * GRID_D + cx)) * CH + q * 8;
    }

    // batch the 8 corner loads for MLP
    uint4 cv[8];
    #pragma unroll
    for (int c = 0; c < 8; ++c)
        cv[c] = *reinterpret_cast<const uint4*>(&g_feat_h[idx[c]]);

    float acc[8] = {0.f, 0.f, 0.f, 0.f, 0.f, 0.f, 0.f, 0.f};
    #pragma unroll
    for (int c = 0; c < 8; ++c) {
        const unsigned u[4] = {cv[c].x, cv[c].y, cv[c].z, cv[c].w};
        #pragma unroll
        for (int kk = 0; kk < 4; ++kk) {
            const half2  h2 = *reinterpret_cast<const half2*>(&u[kk]);
            const float2 f2 = __half22float2(h2);
            acc[kk * 2 + 0] = fmaf(w[c], f2.x, acc[kk * 2 + 0]);
            acc[kk * 2 + 1] = fmaf(w[c], f2.y, acc[kk * 2 + 1]);
        }
    }

    float* op = out + (size_t)p * CH + q * 8;
    *reinterpret_cast<float4*>(op)     = make_float4(acc[0], acc[1], acc[2], acc[3]);
    *reinterpret_cast<float4*>(op + 4) = make_float4(acc[4], acc[5], acc[6], acc[7]);
}

extern "C" void kernel_launch(void* const* d_in, const int* in_sizes, int n_in,
                              void* d_out, int out_size) {
    const float* x       = (const float*)d_in[0];   // (N_POINTS, 3)
    const float* feature = (const float*)d_in[1];   // (32, 128, 128, 128)
    float*       out     = (float*)d_out;           // (N_POINTS, 32)

    transpose_feat<<<NVOX / 256, 256>>>(feature);

    const int total   = N_POINTS * 4;
    const int threads = 256;
    gather_trilinear<<<(total + threads - 1) / threads, threads>>>(x, out);
}